// round 13
// baseline (speedup 1.0000x reference)
#include <cuda_runtime.h>
#include <cuda_bf16.h>

#define NN   4
#define AA   16
#define HH   384
#define WW   384
#define STR  4
#define NB   95
#define NBLK (NB*NB)
#define SEG  (NB*8)
#define NSWEEP 4
#define THRESH_F 2.0f
#define ASTRIDE (NB*8*SEG)   // 577600

// Block outputs: [n][a][bi][li][bj][lj], ~148 MB static (allowed)
__device__ float g_scratch[(size_t)NN * AA * NB * 8 * NB * 8];

// Per-warp smem (floats): m[64][18] | G[16][17] | V[16][17] | r[16]
#define SMS 18
#define GS  17
#define OFF_G 1152
#define OFF_V 1424
#define OFF_R 1696
#define WSM   1712

__global__ __launch_bounds__(128, 6) void llr_pass1(const float* __restrict__ x) {
    __shared__ float sh[4 * WSM];

    const int wid  = threadIdx.x >> 5;
    const int lane = threadIdx.x & 31;
    float* smm = sh + wid * WSM;
    float* sG  = smm + OFF_G;      // becomes W after eigensolve
    float* sV  = smm + OFF_V;
    float* sR  = smm + OFF_R;

    const int id  = blockIdx.x * 4 + wid;
    const int n   = id / NBLK;
    const int blk = id - n * NBLK;
    const int bi  = blk / NB;
    const int bj  = blk - bi * NB;

    const int jg = lane >> 2, kg = lane & 3;
    const int j0 = jg * 2,    k0 = kg * 4;

    // off-diag block map: lanes 4..31 -> (obI < obJ) in 0..7
    int obI = 0, obJ = 1;
    if (lane >= 4) {
        int t = lane - 4, I = 0, rl = 7;
        while (t >= rl) { t -= rl; rl--; I++; }
        obI = I; obJ = I + 1 + t;
    }
    const bool is_par = (lane < 8);

    // ---- gather m (1024 elems, 32/lane)
    {
        const int xbase = (n * AA * HH + bi * STR) * WW + bj * STR;
        #pragma unroll 4
        for (int i = 0; i < 32; i++) {
            int e = lane + i * 32;
            int a = e >> 6, p = e & 63;
            smm[p * SMS + a] = x[xbase + a * (HH * WW) + (p >> 3) * WW + (p & 7)];
        }
    }
    __syncwarp();

    // ---- G = m^T m, 2x4 tile/lane, float2 row reads; V = I
    {
        float g00=0,g01=0,g02=0,g03=0,g10=0,g11=0,g12=0,g13=0;
        #pragma unroll 8
        for (int p = 0; p < 64; p++) {
            const float* row = smm + p * SMS;
            float2 va  = *(const float2*)(row + j0);
            float2 vb0 = *(const float2*)(row + k0);
            float2 vb1 = *(const float2*)(row + k0 + 2);
            g00 += va.x*vb0.x; g01 += va.x*vb0.y; g02 += va.x*vb1.x; g03 += va.x*vb1.y;
            g10 += va.y*vb0.x; g11 += va.y*vb0.y; g12 += va.y*vb1.x; g13 += va.y*vb1.y;
        }
        sG[ j0      * GS + k0] = g00; sG[ j0      * GS + k0+1] = g01;
        sG[ j0      * GS + k0+2] = g02; sG[ j0    * GS + k0+3] = g03;
        sG[(j0 + 1) * GS + k0] = g10; sG[(j0 + 1) * GS + k0+1] = g11;
        sG[(j0 + 1) * GS + k0+2] = g12; sG[(j0 + 1) * GS + k0+3] = g13;
        #pragma unroll
        for (int i = 0; i < 8; i++) {
            int e = lane + i * 32;
            sV[(e >> 4) * GS + (e & 15)] = ((e >> 4) == (e & 15)) ? 1.f : 0.f;
        }
    }
    __syncwarp();

    // ---- pair-block parallel Jacobi, tournament pairing, 15 rounds/sweep
    for (int it = 0; it < NSWEEP * 15; it++) {
        const int r = it % 15;
        auto pq = [&](int k, int& p, int& q) {
            if (k == 0) { p = 15; q = r; }
            else        { p = (r + k) % 15; q = (r + 15 - k) % 15; }
        };

        // params on lanes 0-7 (pair k = lane)
        int pP = 0, qP = 1;
        float app = 1.f, aqq = 1.f, apq = 0.f;
        if (is_par) {
            pq(lane, pP, qP);
            app = sG[pP * GS + pP]; aqq = sG[qP * GS + qP]; apq = sG[pP * GS + qP];
        }
        float d2 = 2.f * apq; d2 = (fabsf(d2) > 1e-30f) ? d2 : 1e-30f;
        float tau = __fdividef(aqq - app, d2);
        float tt  = __fdividef(1.f, fabsf(tau) + sqrtf(1.f + tau * tau));
        tt = (tau < 0.f) ? -tt : tt;
        float c = rsqrtf(1.f + tt * tt);
        float s = tt * c;

        const float cI = __shfl_sync(0xffffffffu, c, obI);
        const float sI = __shfl_sync(0xffffffffu, s, obI);
        const float cJ = __shfl_sync(0xffffffffu, c, obJ);
        const float sJ = __shfl_sync(0xffffffffu, s, obJ);

        // off-diag block read (lanes 4-31)
        int pI, qI, pJ, qJ;
        pq(obI, pI, qI); pq(obJ, pJ, qJ);
        float b00 = 0.f, b01 = 0.f, b10 = 0.f, b11 = 0.f;
        if (lane >= 4) {
            b00 = sG[pI * GS + pJ]; b01 = sG[pI * GS + qJ];
            b10 = sG[qI * GS + pJ]; b11 = sG[qI * GS + qJ];
        }
        __syncwarp();   // all G reads complete before writes

        if (is_par) {   // diag block: exact closed form
            sG[pP * GS + pP] = app - tt * apq;
            sG[qP * GS + qP] = aqq + tt * apq;
            sG[pP * GS + qP] = 0.f;
            sG[qP * GS + pP] = 0.f;
        }
        if (lane >= 4) {  // B' = J_I^T B J_J, plus symmetric mirror
            float m00 = cI*b00 - sI*b10, m01 = cI*b01 - sI*b11;
            float m10 = sI*b00 + cI*b10, m11 = sI*b01 + cI*b11;
            float n00 = cJ*m00 - sJ*m01, n01 = sJ*m00 + cJ*m01;
            float n10 = cJ*m10 - sJ*m11, n11 = sJ*m10 + cJ*m11;
            sG[pI * GS + pJ] = n00; sG[pI * GS + qJ] = n01;
            sG[qI * GS + pJ] = n10; sG[qI * GS + qJ] = n11;
            sG[pJ * GS + pI] = n00; sG[qJ * GS + pI] = n01;
            sG[pJ * GS + qI] = n10; sG[qJ * GS + qI] = n11;
        }

        // V <- V*J: pair kv = lane>>2, rows r0..r0+3 (lane-private elements)
        {
            const int kv = lane >> 2;
            const float cV = __shfl_sync(0xffffffffu, c, kv);
            const float sV2 = __shfl_sync(0xffffffffu, s, kv);
            int pV, qV; pq(kv, pV, qV);
            const int r0 = (lane & 3) * 4;
            float np[4], nq[4];
            #pragma unroll
            for (int i2 = 0; i2 < 4; i2++) {
                float a1 = sV[(r0 + i2) * GS + pV], a2 = sV[(r0 + i2) * GS + qV];
                np[i2] = cV * a1 - sV2 * a2;
                nq[i2] = sV2 * a1 + cV * a2;
            }
            #pragma unroll
            for (int i2 = 0; i2 < 4; i2++) {
                sV[(r0 + i2) * GS + pV] = np[i2];
                sV[(r0 + i2) * GS + qV] = nq[i2];
            }
        }
        __syncwarp();
    }

    // ---- soft-threshold ratios
    if (lane < 16) {
        float sv = sqrtf(fmaxf(sG[lane * GS + lane], 0.f));
        sR[lane] = (sv > THRESH_F) ? (1.f - __fdividef(THRESH_F, sv)) : 0.f;
    }
    __syncwarp();

    // ---- W = V diag(r) V^T, 2x4 tile/lane, in place over sG
    {
        float w00=0,w01=0,w02=0,w03=0,w10=0,w11=0,w12=0,w13=0;
        #pragma unroll
        for (int i2 = 0; i2 < 16; i2++) {
            float rr = sR[i2];
            float a0 = sV[j0 * GS + i2], a1 = sV[(j0 + 1) * GS + i2];
            float b0 = rr * sV[k0 * GS + i2],     b1 = rr * sV[(k0+1) * GS + i2];
            float b2 = rr * sV[(k0+2) * GS + i2], b3 = rr * sV[(k0+3) * GS + i2];
            w00 += a0*b0; w01 += a0*b1; w02 += a0*b2; w03 += a0*b3;
            w10 += a1*b0; w11 += a1*b1; w12 += a1*b2; w13 += a1*b3;
        }
        __syncwarp();
        sG[ j0    * GS + k0] = w00; sG[ j0    * GS + k0+1] = w01;
        sG[ j0    * GS + k0+2] = w02; sG[ j0  * GS + k0+3] = w03;
        sG[(j0+1) * GS + k0] = w10; sG[(j0+1) * GS + k0+1] = w11;
        sG[(j0+1) * GS + k0+2] = w12; sG[(j0+1)* GS + k0+3] = w13;
    }
    __syncwarp();

    // ---- out = m @ W, 8p(stride 8) x 4a tile/lane -> scratch
    {
        const int pg = jg, a0c = kg * 4;
        const int sbase = n * (AA * ASTRIDE) + bi * (8 * SEG) + bj * 8;
        float acc[4][8];
        #pragma unroll
        for (int cc = 0; cc < 4; cc++)
            #pragma unroll
            for (int rr = 0; rr < 8; rr++) acc[cc][rr] = 0.f;
        #pragma unroll 4
        for (int j = 0; j < 16; j++) {
            float wv[4];
            #pragma unroll
            for (int cc = 0; cc < 4; cc++) wv[cc] = sG[j * GS + a0c + cc];
            #pragma unroll
            for (int rr = 0; rr < 8; rr++) {
                float mv = smm[(pg + 8 * rr) * SMS + j];
                #pragma unroll
                for (int cc = 0; cc < 4; cc++) acc[cc][rr] += mv * wv[cc];
            }
        }
        #pragma unroll
        for (int cc = 0; cc < 4; cc++) {
            int abase = sbase + (a0c + cc) * ASTRIDE + pg;
            #pragma unroll
            for (int rr = 0; rr < 8; rr++)
                g_scratch[abase + rr * SEG] = acc[cc][rr];
        }
    }
}

// ---------------------------------------------------------------------------
__global__ __launch_bounds__(128) void llr_pass2(const float* __restrict__ bw,
                                                 float* __restrict__ out) {
    __shared__ float seg[2][SEG];
    const int cta = blockIdx.x;
    const int h   = cta % HH;
    const int na  = cta / HH;
    const int t   = threadIdx.x;

    const int bi_lo = max(0, (h - 4) >> 2);
    const int bi_hi = min(NB - 1, h >> 2);
    const int nbi   = bi_hi - bi_lo + 1;

    for (int b = 0; b < nbi; b++) {
        int bi = bi_lo + b;
        int li = h - bi * STR;
        const float* src = g_scratch + na * ASTRIDE + (bi * 8 + li) * SEG;
        for (int i = t; i < SEG; i += 128) seg[b][i] = src[i];
    }
    __syncthreads();

    #pragma unroll
    for (int i = 0; i < 3; i++) {
        int w = t + i * 128;
        int bj_lo = max(0, (w - 4) >> 2);
        int bj_hi = min(NB - 1, w >> 2);
        float acc = 0.f;
        for (int b = 0; b < nbi; b++)
            for (int bj = bj_lo; bj <= bj_hi; bj++)
                acc += seg[b][bj * 8 + (w - bj * STR)];
        out[(na * HH + h) * WW + w] = acc / bw[h * WW + w];
    }
}

// no-op launches pad the per-call launch count to 5 so ncu's fixed "-s 5"
// lands on llr_pass1 (launch idx 5) instead of always profiling pass2.
__global__ void llr_nop() {}

extern "C" void kernel_launch(void* const* d_in, const int* in_sizes, int n_in,
                              void* d_out, int out_size) {
    (void)n_in; (void)out_size;
    const float* x;
    const float* bw;
    if (in_sizes[0] == NN * AA * HH * WW) { x = (const float*)d_in[0]; bw = (const float*)d_in[1]; }
    else                                  { x = (const float*)d_in[1]; bw = (const float*)d_in[0]; }
    float* out = (float*)d_out;

    llr_pass1<<<(NN * NBLK) / 4, 128>>>(x);
    llr_pass2<<<NN * AA * HH, 128>>>(bw, out);
    llr_nop<<<1, 32>>>();
    llr_nop<<<1, 32>>>();
    llr_nop<<<1, 32>>>();
}

// round 15
// speedup vs baseline: 1.4253x; 1.4253x over previous
#include <cuda_runtime.h>
#include <cuda_bf16.h>

#define NN   4
#define AA   16
#define HH   384
#define WW   384
#define STR  4
#define NB   95
#define NBLK (NB*NB)
#define SEG  (NB*8)
#define NITER 54             // 3.6 sweeps of the 15-round tournament
#define THRESH_F 2.0f
#define ASTRIDE (NB*8*SEG)   // 577600

// Block outputs: [n][a][bi][li][bj][lj], ~148 MB static (allowed)
__device__ float g_scratch[(size_t)NN * AA * NB * 8 * NB * 8];

// Per-warp smem (floats): m[64][18] | G[16][17] | V[16][17] | r[16]
#define SMS 18
#define GS  17
#define OFF_G 1152
#define OFF_V 1424
#define OFF_R 1696
#define WSM   1712

// ---------------------------------------------------------------------------
// Pass 1: one WARP per (n, block). 4 independent warps/CTA. R11 structure:
// redundant per-4-lane rotation params, 3-phase smem Jacobi (conflict-light),
// register-tiled Gram/W/GEMM.
// ---------------------------------------------------------------------------
__global__ __launch_bounds__(128, 6) void llr_pass1(const float* __restrict__ x) {
    __shared__ float sh[4 * WSM];

    const int wid  = threadIdx.x >> 5;
    const int lane = threadIdx.x & 31;
    float* smm = sh + wid * WSM;
    float* sG  = smm + OFF_G;      // becomes W after eigensolve
    float* sV  = smm + OFF_V;
    float* sR  = smm + OFF_R;

    const int id  = blockIdx.x * 4 + wid;
    const int n   = id / NBLK;
    const int blk = id - n * NBLK;
    const int bi  = blk / NB;
    const int bj  = blk - bi * NB;

    const int jg = lane >> 2, kg = lane & 3;
    const int j0 = jg * 2,    k0 = kg * 4;

    // ---- gather m (1024 elems, 32/lane; lj runs 32B-contiguous in gmem)
    {
        const int xbase = (n * AA * HH + bi * STR) * WW + bj * STR;
        #pragma unroll 4
        for (int i = 0; i < 32; i++) {
            int e = lane + i * 32;
            int a = e >> 6, p = e & 63;
            smm[p * SMS + a] = x[xbase + a * (HH * WW) + (p >> 3) * WW + (p & 7)];
        }
    }
    __syncwarp();

    // ---- G = m^T m, 2x4 tile/lane, float2 row reads (broadcast-friendly); V=I
    {
        float g00=0,g01=0,g02=0,g03=0,g10=0,g11=0,g12=0,g13=0;
        #pragma unroll 8
        for (int p = 0; p < 64; p++) {
            const float* row = smm + p * SMS;
            float2 va  = *(const float2*)(row + j0);
            float2 vb0 = *(const float2*)(row + k0);
            float2 vb1 = *(const float2*)(row + k0 + 2);
            g00 += va.x*vb0.x; g01 += va.x*vb0.y; g02 += va.x*vb1.x; g03 += va.x*vb1.y;
            g10 += va.y*vb0.x; g11 += va.y*vb0.y; g12 += va.y*vb1.x; g13 += va.y*vb1.y;
        }
        sG[ j0      * GS + k0    ] = g00; sG[ j0      * GS + k0 + 1] = g01;
        sG[ j0      * GS + k0 + 2] = g02; sG[ j0      * GS + k0 + 3] = g03;
        sG[(j0 + 1) * GS + k0    ] = g10; sG[(j0 + 1) * GS + k0 + 1] = g11;
        sG[(j0 + 1) * GS + k0 + 2] = g12; sG[(j0 + 1) * GS + k0 + 3] = g13;
        #pragma unroll
        for (int i = 0; i < 8; i++) {
            int e = lane + i * 32;
            sV[(e >> 4) * GS + (e & 15)] = ((e >> 4) == (e & 15)) ? 1.f : 0.f;
        }
    }
    __syncwarp();

    // ---- parallel cyclic Jacobi: 8 disjoint rotations/round, tournament
    //      pairing. All 4 lanes of a pair compute (c,s) redundantly
    //      (branchless, broadcast smem reads).
    {
        const int k   = lane >> 2;      // pair id 0..7
        const int sub = lane & 3;       // segment 0..3
        const int r0  = sub * 4;

        for (int it = 0; it < NITER; it++) {
            int r = it % 15;
            int p, q;
            if (k == 0) { p = 15; q = r; }
            else        { p = (r + k) % 15; q = (r + 15 - k) % 15; }

            float apq = sG[p * GS + q];
            float app = sG[p * GS + p], aqq = sG[q * GS + q];
            float d2  = 2.f * apq;
            d2 = (fabsf(d2) > 1e-30f) ? d2 : 1e-30f;
            float tau = __fdividef(aqq - app, d2);
            float tt  = __fdividef(1.f, fabsf(tau) + sqrtf(1.f + tau * tau));
            tt = (tau < 0.f) ? -tt : tt;
            float c = rsqrtf(1.f + tt * tt);
            float s = tt * c;
            __syncwarp();   // params fully read before any G write

            float np[4], nq[4];

            // Phase A: G <- G*J (columns p,q; this lane's 4 rows)
            #pragma unroll
            for (int i2 = 0; i2 < 4; i2++) {
                float a1 = sG[(r0 + i2) * GS + p], a2 = sG[(r0 + i2) * GS + q];
                np[i2] = c * a1 - s * a2;
                nq[i2] = s * a1 + c * a2;
            }
            #pragma unroll
            for (int i2 = 0; i2 < 4; i2++) {
                sG[(r0 + i2) * GS + p] = np[i2];
                sG[(r0 + i2) * GS + q] = nq[i2];
            }
            __syncwarp();

            // Phase B: G <- J^T*G (rows p,q; this lane's 4 columns)
            #pragma unroll
            for (int i2 = 0; i2 < 4; i2++) {
                float a1 = sG[p * GS + r0 + i2], a2 = sG[q * GS + r0 + i2];
                np[i2] = c * a1 - s * a2;
                nq[i2] = s * a1 + c * a2;
            }
            #pragma unroll
            for (int i2 = 0; i2 < 4; i2++) {
                sG[p * GS + r0 + i2] = np[i2];
                sG[q * GS + r0 + i2] = nq[i2];
            }

            // Phase C: V <- V*J (V-only; ordered vs next iter by loop-end sync)
            #pragma unroll
            for (int i2 = 0; i2 < 4; i2++) {
                float a1 = sV[(r0 + i2) * GS + p], a2 = sV[(r0 + i2) * GS + q];
                np[i2] = c * a1 - s * a2;
                nq[i2] = s * a1 + c * a2;
            }
            #pragma unroll
            for (int i2 = 0; i2 < 4; i2++) {
                sV[(r0 + i2) * GS + p] = np[i2];
                sV[(r0 + i2) * GS + q] = nq[i2];
            }
            __syncwarp();
        }
    }

    // ---- spectral soft-threshold ratios: r_i = max(sqrt(l)-T, 0)/sqrt(l)
    if (lane < 16) {
        float sv = sqrtf(fmaxf(sG[lane * GS + lane], 0.f));
        sR[lane] = (sv > THRESH_F) ? (1.f - __fdividef(THRESH_F, sv)) : 0.f;
    }
    __syncwarp();

    // ---- W = V diag(r) V^T, 2x4 tile/lane, in place over sG
    {
        float w00=0,w01=0,w02=0,w03=0,w10=0,w11=0,w12=0,w13=0;
        #pragma unroll
        for (int i2 = 0; i2 < 16; i2++) {
            float rr = sR[i2];
            float a0 = sV[j0 * GS + i2], a1 = sV[(j0 + 1) * GS + i2];
            float b0 = rr * sV[k0 * GS + i2],       b1 = rr * sV[(k0 + 1) * GS + i2];
            float b2 = rr * sV[(k0 + 2) * GS + i2], b3 = rr * sV[(k0 + 3) * GS + i2];
            w00 += a0*b0; w01 += a0*b1; w02 += a0*b2; w03 += a0*b3;
            w10 += a1*b0; w11 += a1*b1; w12 += a1*b2; w13 += a1*b3;
        }
        __syncwarp();   // all V reads done before sG overwrite
        sG[ j0      * GS + k0    ] = w00; sG[ j0      * GS + k0 + 1] = w01;
        sG[ j0      * GS + k0 + 2] = w02; sG[ j0      * GS + k0 + 3] = w03;
        sG[(j0 + 1) * GS + k0    ] = w10; sG[(j0 + 1) * GS + k0 + 1] = w11;
        sG[(j0 + 1) * GS + k0 + 2] = w12; sG[(j0 + 1) * GS + k0 + 3] = w13;
    }
    __syncwarp();

    // ---- out = m @ W, 8p(stride 8) x 4a tile/lane -> scratch
    {
        const int pg = jg, a0c = kg * 4;
        const int sbase = n * (AA * ASTRIDE) + bi * (8 * SEG) + bj * 8;
        float acc[4][8];
        #pragma unroll
        for (int cc = 0; cc < 4; cc++)
            #pragma unroll
            for (int rr = 0; rr < 8; rr++) acc[cc][rr] = 0.f;
        #pragma unroll 4
        for (int j = 0; j < 16; j++) {
            float wv[4];
            #pragma unroll
            for (int cc = 0; cc < 4; cc++) wv[cc] = sG[j * GS + a0c + cc];
            #pragma unroll
            for (int rr = 0; rr < 8; rr++) {
                float mv = smm[(pg + 8 * rr) * SMS + j];
                #pragma unroll
                for (int cc = 0; cc < 4; cc++) acc[cc][rr] += mv * wv[cc];
            }
        }
        #pragma unroll
        for (int cc = 0; cc < 4; cc++) {
            int abase = sbase + (a0c + cc) * ASTRIDE + pg;
            #pragma unroll
            for (int rr = 0; rr < 8; rr++)
                g_scratch[abase + rr * SEG] = acc[cc][rr];
        }
    }
}

// ---------------------------------------------------------------------------
// Pass 2: one CTA per output row (n,a,h). Pure gather-sum, deterministic,
// atomic-free, fully coalesced.
// ---------------------------------------------------------------------------
__global__ __launch_bounds__(128) void llr_pass2(const float* __restrict__ bw,
                                                 float* __restrict__ out) {
    __shared__ float seg[2][SEG];
    const int cta = blockIdx.x;
    const int h   = cta % HH;
    const int na  = cta / HH;
    const int t   = threadIdx.x;

    const int bi_lo = max(0, (h - 4) >> 2);
    const int bi_hi = min(NB - 1, h >> 2);
    const int nbi   = bi_hi - bi_lo + 1;

    for (int b = 0; b < nbi; b++) {
        int bi = bi_lo + b;
        int li = h - bi * STR;
        const float* src = g_scratch + na * ASTRIDE + (bi * 8 + li) * SEG;
        for (int i = t; i < SEG; i += 128) seg[b][i] = src[i];
    }
    __syncthreads();

    #pragma unroll
    for (int i = 0; i < 3; i++) {
        int w = t + i * 128;
        int bj_lo = max(0, (w - 4) >> 2);
        int bj_hi = min(NB - 1, w >> 2);
        float acc = 0.f;
        for (int b = 0; b < nbi; b++)
            for (int bj = bj_lo; bj <= bj_hi; bj++)
                acc += seg[b][bj * 8 + (w - bj * STR)];
        out[(na * HH + h) * WW + w] = acc / bw[h * WW + w];
    }
}

// ---------------------------------------------------------------------------
extern "C" void kernel_launch(void* const* d_in, const int* in_sizes, int n_in,
                              void* d_out, int out_size) {
    (void)n_in; (void)out_size;
    const float* x;
    const float* bw;
    if (in_sizes[0] == NN * AA * HH * WW) { x = (const float*)d_in[0]; bw = (const float*)d_in[1]; }
    else                                  { x = (const float*)d_in[1]; bw = (const float*)d_in[0]; }
    float* out = (float*)d_out;

    llr_pass1<<<(NN * NBLK) / 4, 128>>>(x);
    llr_pass2<<<NN * AA * HH, 128>>>(bw, out);
}